// round 15
// baseline (speedup 1.0000x reference)
#include <cuda_runtime.h>
#include <cuda_bf16.h>

#define NN 100000     // nodes
#define NE 1600000    // edges
#define NG 2048       // graphs
#define NFD 64        // node feature dim
#define DD 32         // hidden dim
#define BN_EPS 1e-5f
#define SCAN_B 512
#define NSB 196       // ceil(NN/SCAN_B)
#define NMB 1563      // ceil(NN/64) blocks for fused layer kernels

// ---------------- scratch (zero at load; k_cleanup restores zeros each call) ----
__device__ int    g_rowptr[NN + 1];
__device__ int    g_rowcur[NN];        // histogram counts, then scatter cursors (0 at entry)
__device__ int    g_csrc[NE];          // CSR: src node ids grouped by dst
__device__ int    g_bsum[256];
__device__ int    g_gstart[NG + 1];    // graph row boundaries (fully rewritten each call)
__device__ float  g_ta[NN * DD];
__device__ float  g_tb[NN * DD];
__device__ double g_stats[5 * 64];     // per layer: [sum(32) | sumsq(32)] (0 at entry)
__device__ float  g_pooled[NG * DD];
__device__ float  g_s1[NG * 256];
__device__ float  g_z[NG * 256];
__device__ float  g_z1[NG * 1024];
__device__ float  g_z2[NG * 256];

// ---------------- CSR build: 4 launches ----------------
__global__ void k_hist(const int* __restrict__ ei) {
    int t = blockIdx.x * blockDim.x + threadIdx.x;
    if (t < NE) atomicAdd(&g_rowcur[ei[NE + t]], 1);
}

__global__ void k_scan1() {
    __shared__ int sh[SCAN_B];
    int t = threadIdx.x, b = blockIdx.x;
    int i = b * SCAN_B + t;
    int v = (i < NN) ? g_rowcur[i] : 0;
    sh[t] = v; __syncthreads();
    for (int off = 1; off < SCAN_B; off <<= 1) {
        int a = (t >= off) ? sh[t - off] : 0;
        __syncthreads();
        sh[t] += a;
        __syncthreads();
    }
    if (i < NN) g_rowptr[i] = sh[t] - v;
    if (t == SCAN_B - 1) g_bsum[b] = sh[t];
}

// merged scan2+scan3: each 256-thread block shares one i>>9 value,
// so its bsum-prefix is a single warp-reduced sum.
__global__ void k_scan23() {
    __shared__ int spre;
    int b = blockIdx.x;
    int sb = b >> 1;   // i>>9 is constant across this block
    if (threadIdx.x < 32) {
        int s = 0;
        for (int j = threadIdx.x; j < sb; j += 32) s += g_bsum[j];
        #pragma unroll
        for (int o = 16; o; o >>= 1) s += __shfl_down_sync(0xffffffffu, s, o);
        if (threadIdx.x == 0) spre = s;
    }
    __syncthreads();
    int i = b * 256 + threadIdx.x;
    if (i < NN) {
        int rp = g_rowptr[i] + spre;
        g_rowptr[i] = rp;
        g_rowcur[i] = rp;
    }
    if (i == 0) g_rowptr[NN] = NE;
}

__global__ void k_scatter(const int* __restrict__ ei) {
    int t = blockIdx.x * blockDim.x + threadIdx.x;
    if (t >= NE) return;
    int d = ei[NE + t];
    int pos = atomicAdd(&g_rowcur[d], 1);
    g_csrc[pos] = ei[t];
}

// ---------------- shared MLP core: As[64xK] -> tout rows, + BN stats ----------
__device__ __forceinline__ void mlp_core(
    float* As, float* C1, const float* W1, const float* W2,
    const float* sba, const float* sbb,
    int K, int r0, float* __restrict__ tout, double* __restrict__ stats_out, int tid)
{
    int ty = tid >> 3, tx = tid & 7;
    float acc[4][4] = {};
    for (int k = 0; k < K; k++) {
        float a0 = As[(ty * 4 + 0) * 65 + k];
        float a1 = As[(ty * 4 + 1) * 65 + k];
        float a2 = As[(ty * 4 + 2) * 65 + k];
        float a3 = As[(ty * 4 + 3) * 65 + k];
        float w0 = W1[k * DD + tx * 4 + 0];
        float w1 = W1[k * DD + tx * 4 + 1];
        float w2 = W1[k * DD + tx * 4 + 2];
        float w3 = W1[k * DD + tx * 4 + 3];
        acc[0][0] = fmaf(a0, w0, acc[0][0]); acc[0][1] = fmaf(a0, w1, acc[0][1]);
        acc[0][2] = fmaf(a0, w2, acc[0][2]); acc[0][3] = fmaf(a0, w3, acc[0][3]);
        acc[1][0] = fmaf(a1, w0, acc[1][0]); acc[1][1] = fmaf(a1, w1, acc[1][1]);
        acc[1][2] = fmaf(a1, w2, acc[1][2]); acc[1][3] = fmaf(a1, w3, acc[1][3]);
        acc[2][0] = fmaf(a2, w0, acc[2][0]); acc[2][1] = fmaf(a2, w1, acc[2][1]);
        acc[2][2] = fmaf(a2, w2, acc[2][2]); acc[2][3] = fmaf(a2, w3, acc[2][3]);
        acc[3][0] = fmaf(a3, w0, acc[3][0]); acc[3][1] = fmaf(a3, w1, acc[3][1]);
        acc[3][2] = fmaf(a3, w2, acc[3][2]); acc[3][3] = fmaf(a3, w3, acc[3][3]);
    }
    #pragma unroll
    for (int i = 0; i < 4; i++)
        #pragma unroll
        for (int j = 0; j < 4; j++)
            C1[(ty * 4 + i) * 33 + tx * 4 + j] = fmaxf(acc[i][j] + sba[tx * 4 + j], 0.f);
    __syncthreads();

    float acc2[4][4] = {};
    #pragma unroll 8
    for (int k = 0; k < DD; k++) {
        float a0 = C1[(ty * 4 + 0) * 33 + k];
        float a1 = C1[(ty * 4 + 1) * 33 + k];
        float a2 = C1[(ty * 4 + 2) * 33 + k];
        float a3 = C1[(ty * 4 + 3) * 33 + k];
        float w0 = W2[k * DD + tx * 4 + 0];
        float w1 = W2[k * DD + tx * 4 + 1];
        float w2 = W2[k * DD + tx * 4 + 2];
        float w3 = W2[k * DD + tx * 4 + 3];
        acc2[0][0] = fmaf(a0, w0, acc2[0][0]); acc2[0][1] = fmaf(a0, w1, acc2[0][1]);
        acc2[0][2] = fmaf(a0, w2, acc2[0][2]); acc2[0][3] = fmaf(a0, w3, acc2[0][3]);
        acc2[1][0] = fmaf(a1, w0, acc2[1][0]); acc2[1][1] = fmaf(a1, w1, acc2[1][1]);
        acc2[1][2] = fmaf(a1, w2, acc2[1][2]); acc2[1][3] = fmaf(a1, w3, acc2[1][3]);
        acc2[2][0] = fmaf(a2, w0, acc2[2][0]); acc2[2][1] = fmaf(a2, w1, acc2[2][1]);
        acc2[2][2] = fmaf(a2, w2, acc2[2][2]); acc2[2][3] = fmaf(a2, w3, acc2[2][3]);
        acc2[3][0] = fmaf(a3, w0, acc2[3][0]); acc2[3][1] = fmaf(a3, w1, acc2[3][1]);
        acc2[3][2] = fmaf(a3, w2, acc2[3][2]); acc2[3][3] = fmaf(a3, w3, acc2[3][3]);
    }
    __syncthreads();   // done reading As; reuse for stats staging
    #pragma unroll
    for (int i = 0; i < 4; i++) {
        int rr = r0 + ty * 4 + i;
        #pragma unroll
        for (int j = 0; j < 4; j++) {
            int c = tx * 4 + j;
            float v = acc2[i][j] + sbb[c];
            if (rr < NN) {
                tout[(long)rr * DD + c] = v;
                As[(ty * 4 + i) * 65 + c] = v;
            } else {
                As[(ty * 4 + i) * 65 + c] = 0.f;
            }
        }
    }
    __syncthreads();
    if (tid < DD) {
        float s = 0.f, q = 0.f;
        #pragma unroll 8
        for (int r = 0; r < 64; r++) {
            float v = As[r * 65 + tid];
            s += v;
            q = fmaf(v, v, q);
        }
        atomicAdd(&stats_out[tid], (double)s);
        atomicAdd(&stats_out[32 + tid], (double)q);
    }
}

// ---------------- fused layer 1: gather(x, K=64) in-tile + MLP ----------------
__global__ void k_layer1f(const float* __restrict__ x, float* __restrict__ tout,
                          const float* __restrict__ wa, const float* __restrict__ ba,
                          const float* __restrict__ wb, const float* __restrict__ bb,
                          double* __restrict__ stats_out) {
    __shared__ float As[64 * 65];
    __shared__ float W1[NFD * DD];
    __shared__ float W2[DD * DD];
    __shared__ float C1[64 * 33];
    __shared__ float sba[DD], sbb[DD];
    int tid = threadIdx.x;
    int r0 = blockIdx.x * 64;
    for (int i = tid; i < (NFD * DD) / 4; i += 128)
        reinterpret_cast<float4*>(W1)[i] = reinterpret_cast<const float4*>(wa)[i];
    for (int i = tid; i < (DD * DD) / 4; i += 128)
        reinterpret_cast<float4*>(W2)[i] = reinterpret_cast<const float4*>(wb)[i];
    if (tid < DD) { sba[tid] = ba[tid]; sbb[tid] = bb[tid]; }

    int lane = tid & 31, warp = tid >> 5;
    for (int row = warp; row < 64; row += 4) {
        int r = r0 + row;
        float a0 = 0.f, a1 = 0.f;
        if (r < NN) {
            a0 = x[r * NFD + lane];
            a1 = x[r * NFD + 32 + lane];
            int e = g_rowptr[r], end = g_rowptr[r + 1];
            for (; e + 4 <= end; e += 4) {
                int s0 = g_csrc[e], s1 = g_csrc[e + 1], s2 = g_csrc[e + 2], s3 = g_csrc[e + 3];
                float u0 = x[s0 * NFD + lane],      v0 = x[s0 * NFD + 32 + lane];
                float u1 = x[s1 * NFD + lane],      v1 = x[s1 * NFD + 32 + lane];
                float u2 = x[s2 * NFD + lane],      v2 = x[s2 * NFD + 32 + lane];
                float u3 = x[s3 * NFD + lane],      v3 = x[s3 * NFD + 32 + lane];
                a0 += (u0 + u1) + (u2 + u3);
                a1 += (v0 + v1) + (v2 + v3);
            }
            for (; e < end; e++) {
                int s = g_csrc[e];
                a0 += x[s * NFD + lane];
                a1 += x[s * NFD + 32 + lane];
            }
        }
        As[row * 65 + lane] = a0;
        As[row * 65 + 32 + lane] = a1;
    }
    __syncthreads();
    mlp_core(As, C1, W1, W2, sba, sbb, NFD, r0, tout, stats_out, tid);
}

// ---------------- fused layers 2-5: BN-relu gather (K=32) in-tile + MLP --------
__global__ void k_layerf(const float* __restrict__ tin, float* __restrict__ tout,
                         const float* __restrict__ wa, const float* __restrict__ ba,
                         const float* __restrict__ wb, const float* __restrict__ bb,
                         const float* __restrict__ bng, const float* __restrict__ bnb,
                         const double* __restrict__ stats_in, double* __restrict__ stats_out) {
    __shared__ float As[64 * 65];
    __shared__ float W1[DD * DD];
    __shared__ float W2[DD * DD];
    __shared__ float C1[64 * 33];
    __shared__ float sba[DD], sbb[DD], ssc[DD], ssh[DD];
    int tid = threadIdx.x;
    int r0 = blockIdx.x * 64;
    for (int i = tid; i < (DD * DD) / 4; i += 128) {
        reinterpret_cast<float4*>(W1)[i] = reinterpret_cast<const float4*>(wa)[i];
        reinterpret_cast<float4*>(W2)[i] = reinterpret_cast<const float4*>(wb)[i];
    }
    if (tid < DD) {
        sba[tid] = ba[tid]; sbb[tid] = bb[tid];
        double mu  = stats_in[tid] / (double)NN;
        double var = stats_in[32 + tid] / (double)NN - mu * mu;
        float sc = bng[tid] * rsqrtf((float)var + BN_EPS);
        ssc[tid] = sc;
        ssh[tid] = bnb[tid] - (float)mu * sc;
    }
    __syncthreads();

    int lane = tid & 31, warp = tid >> 5;
    float sc = ssc[lane], sh = ssh[lane];
    for (int row = warp; row < 64; row += 4) {
        int r = r0 + row;
        float a = 0.f;
        if (r < NN) {
            a = fmaxf(fmaf(tin[r * DD + lane], sc, sh), 0.f);
            int e = g_rowptr[r], end = g_rowptr[r + 1];
            for (; e + 8 <= end; e += 8) {
                int s0 = g_csrc[e],     s1 = g_csrc[e + 1];
                int s2 = g_csrc[e + 2], s3 = g_csrc[e + 3];
                int s4 = g_csrc[e + 4], s5 = g_csrc[e + 5];
                int s6 = g_csrc[e + 6], s7 = g_csrc[e + 7];
                float v0 = tin[s0 * DD + lane], v1 = tin[s1 * DD + lane];
                float v2 = tin[s2 * DD + lane], v3 = tin[s3 * DD + lane];
                float v4 = tin[s4 * DD + lane], v5 = tin[s5 * DD + lane];
                float v6 = tin[s6 * DD + lane], v7 = tin[s7 * DD + lane];
                v0 = fmaxf(fmaf(v0, sc, sh), 0.f); v1 = fmaxf(fmaf(v1, sc, sh), 0.f);
                v2 = fmaxf(fmaf(v2, sc, sh), 0.f); v3 = fmaxf(fmaf(v3, sc, sh), 0.f);
                v4 = fmaxf(fmaf(v4, sc, sh), 0.f); v5 = fmaxf(fmaf(v5, sc, sh), 0.f);
                v6 = fmaxf(fmaf(v6, sc, sh), 0.f); v7 = fmaxf(fmaf(v7, sc, sh), 0.f);
                a += ((v0 + v1) + (v2 + v3)) + ((v4 + v5) + (v6 + v7));
            }
            for (; e < end; e++) {
                int s = g_csrc[e];
                a += fmaxf(fmaf(tin[s * DD + lane], sc, sh), 0.f);
            }
        }
        As[row * 65 + lane] = a;
    }
    __syncthreads();
    mlp_core(As, C1, W1, W2, sba, sbb, DD, r0, tout, stats_out, tid);
}

// ---------------- graph boundaries from sorted batch ----------------
__global__ void k_gbounds(const int* __restrict__ batch) {
    int i = blockIdx.x * blockDim.x + threadIdx.x;
    if (i >= NN) return;
    int b0 = batch[i];
    int b1 = (i + 1 < NN) ? batch[i + 1] : NG;
    for (int g = b0 + 1; g <= b1; g++) g_gstart[g] = i + 1;
    if (i == 0)
        for (int g = 0; g <= b0; g++) g_gstart[g] = 0;
}

// ---------------- pooling: warp-per-graph segmented sum (no atomics) ----------
__global__ void k_pool(const float* __restrict__ tin,
                       const float* __restrict__ bng, const float* __restrict__ bnb,
                       const double* __restrict__ stats_in) {
    __shared__ float ssc[DD], ssh[DD];
    int tid = threadIdx.x;
    if (tid < DD) {
        double mu  = stats_in[tid] / (double)NN;
        double var = stats_in[32 + tid] / (double)NN - mu * mu;
        float sc = bng[tid] * rsqrtf((float)var + BN_EPS);
        ssc[tid] = sc;
        ssh[tid] = bnb[tid] - (float)mu * sc;
    }
    __syncthreads();
    int lane = tid & 31;
    int g = (blockIdx.x * blockDim.x + tid) >> 5;
    if (g >= NG) return;
    float sc = ssc[lane], sh = ssh[lane];
    int lo = g_gstart[g], hi = g_gstart[g + 1];
    float acc = 0.f;
    for (int r = lo; r < hi; r++)
        acc += fmaxf(fmaf(tin[r * DD + lane], sc, sh), 0.f);
    g_pooled[g * DD + lane] = acc;
}

// ---------------- head GEMM: 64x64 tile, BK=32, float4 loads ----------------
__global__ void k_gemm(const float* __restrict__ A, const float* __restrict__ W,
                       const float* __restrict__ bias, float* __restrict__ C,
                       int M, int K, int Nc, int ldc, int do_relu) {
    const int BM = 64, BN = 64, BK = 32;
    __shared__ float As[BK][BM + 1];
    __shared__ float Ws[BK][BN];
    int tx = threadIdx.x & 15, ty = threadIdx.x >> 4;
    int row0 = blockIdx.y * BM, col0 = blockIdx.x * BN;
    float acc[4][4] = {};
    for (int k0 = 0; k0 < K; k0 += BK) {
        for (int i = threadIdx.x; i < BM * (BK / 4); i += 256) {
            int m = i >> 3, q = i & 7;
            float4 v = reinterpret_cast<const float4*>(A + (long)(row0 + m) * K + k0)[q];
            As[q * 4 + 0][m] = v.x;
            As[q * 4 + 1][m] = v.y;
            As[q * 4 + 2][m] = v.z;
            As[q * 4 + 3][m] = v.w;
        }
        for (int i = threadIdx.x; i < BK * (BN / 4); i += 256) {
            int kk = i >> 4, q = i & 15;
            float4 v = reinterpret_cast<const float4*>(W + (long)(k0 + kk) * Nc + col0)[q];
            reinterpret_cast<float4*>(&Ws[kk][0])[q] = v;
        }
        __syncthreads();
        #pragma unroll
        for (int kk = 0; kk < BK; kk++) {
            float a[4], w[4];
            #pragma unroll
            for (int i = 0; i < 4; i++) a[i] = As[kk][ty * 4 + i];
            #pragma unroll
            for (int j = 0; j < 4; j++) w[j] = Ws[kk][tx * 4 + j];
            #pragma unroll
            for (int i = 0; i < 4; i++)
                #pragma unroll
                for (int j = 0; j < 4; j++) acc[i][j] = fmaf(a[i], w[j], acc[i][j]);
        }
        __syncthreads();
    }
    #pragma unroll
    for (int i = 0; i < 4; i++) {
        int r = row0 + ty * 4 + i;
        #pragma unroll
        for (int j = 0; j < 4; j++) {
            int c = col0 + tx * 4 + j;
            float v = acc[i][j] + bias[c];
            if (do_relu) v = fmaxf(v, 0.f);
            C[(long)r * ldc + c] = v;
        }
    }
}

__global__ void k_out(const float* __restrict__ ow, const float* __restrict__ ob,
                      float* __restrict__ out) {
    int warp = (blockIdx.x * blockDim.x + threadIdx.x) >> 5;
    int lane = threadIdx.x & 31;
    if (warp >= NG) return;
    float acc = 0.f;
    #pragma unroll
    for (int k = lane; k < 256; k += 32)
        acc = fmaf(g_z2[warp * 256 + k], ow[k], acc);
    #pragma unroll
    for (int o = 16; o; o >>= 1) acc += __shfl_down_sync(0xffffffffu, acc, o);
    if (lane == 0) out[warp] = acc + ob[0];
}

// restore load-time-zero state for the next replay
__global__ void k_cleanup() {
    int i = blockIdx.x * blockDim.x + threadIdx.x;
    if (i < NN) g_rowcur[i] = 0;
    if (i < 5 * 64) g_stats[i] = 0.0;
}

// ---------------- launch ----------------
extern "C" void kernel_launch(void* const* d_in, const int* in_sizes, int n_in,
                              void* d_out, int out_size) {
    const float* x     = (const float*)d_in[0];
    const int*   ei    = (const int*)d_in[1];
    const int*   batch = (const int*)d_in[2];
    const float* sf    = (const float*)d_in[3];
    const float* w1a   = (const float*)d_in[4];
    const float* b1a   = (const float*)d_in[5];
    const float* ws_a  = (const float*)d_in[6];
    const float* bs_a  = (const float*)d_in[7];
    const float* ws_b  = (const float*)d_in[8];
    const float* bs_b  = (const float*)d_in[9];
    const float* bn_g  = (const float*)d_in[10];
    const float* bn_b  = (const float*)d_in[11];
    const float* fcg_w = (const float*)d_in[12];
    const float* fcg_b = (const float*)d_in[13];
    const float* fs1_w = (const float*)d_in[14];
    const float* fs1_b = (const float*)d_in[15];
    const float* fs2_w = (const float*)d_in[16];
    const float* fs2_b = (const float*)d_in[17];
    const float* fc1_w = (const float*)d_in[18];
    const float* fc1_b = (const float*)d_in[19];
    const float* fc2_w = (const float*)d_in[20];
    const float* fc2_b = (const float*)d_in[21];
    const float* out_w = (const float*)d_in[22];
    const float* out_b = (const float*)d_in[23];
    float* out = (float*)d_out;

    float *p_ta, *p_tb, *p_pooled, *p_s1, *p_z, *p_z1, *p_z2;
    double* p_stats;
    cudaGetSymbolAddress((void**)&p_ta, g_ta);
    cudaGetSymbolAddress((void**)&p_tb, g_tb);
    cudaGetSymbolAddress((void**)&p_stats, g_stats);
    cudaGetSymbolAddress((void**)&p_pooled, g_pooled);
    cudaGetSymbolAddress((void**)&p_s1, g_s1);
    cudaGetSymbolAddress((void**)&p_z, g_z);
    cudaGetSymbolAddress((void**)&p_z1, g_z1);
    cudaGetSymbolAddress((void**)&p_z2, g_z2);

    const int TB = 256;

    // CSR build: 4 launches -> k_scatter is launch #4 (profiled by ncu)
    k_hist<<<(NE + TB - 1) / TB, TB>>>(ei);
    k_scan1<<<NSB, SCAN_B>>>();
    k_scan23<<<(NN + 255) / 256, 256>>>();
    k_scatter<<<(NE + TB - 1) / TB, TB>>>(ei);

    // fused layers (gather in-tile + MLP + BN stats)
    k_layer1f<<<NMB, 128>>>(x, p_ta, w1a, b1a, ws_b, bs_b, p_stats);
    float* bufs[2] = { p_ta, p_tb };
    for (int i = 1; i < 5; i++) {
        const float* tin = bufs[(i + 1) & 1];
        float* tout = bufs[i & 1];
        k_layerf<<<NMB, 128>>>(tin, tout,
                               ws_a + (i - 1) * DD * DD, bs_a + (i - 1) * DD,
                               ws_b + i * DD * DD, bs_b + i * DD,
                               bn_g + (i - 1) * DD, bn_b + (i - 1) * DD,
                               p_stats + (i - 1) * 64, p_stats + i * 64);
    }
    float* last = bufs[4 & 1];  // p_ta holds layer-5 pre-BN output

    // pool: boundaries + warp-per-graph segmented sum (BN folded)
    k_gbounds<<<(NN + TB - 1) / TB, TB>>>(batch);
    k_pool<<<(NG * 32 + TB - 1) / TB, TB>>>(last, bn_g + 4 * DD, bn_b + 4 * DD,
                                            p_stats + 4 * 64);

    // head
    k_gemm<<<dim3(128 / 64, NG / 64), 256>>>(p_pooled, fcg_w, fcg_b, p_z,
                                             NG, DD, 128, 256, 1);
    k_gemm<<<dim3(256 / 64, NG / 64), 256>>>(sf, fs1_w, fs1_b, p_s1,
                                             NG, 512, 256, 256, 1);
    k_gemm<<<dim3(128 / 64, NG / 64), 256>>>(p_s1, fs2_w, fs2_b, p_z + 128,
                                             NG, 256, 128, 256, 1);
    k_gemm<<<dim3(1024 / 64, NG / 64), 256>>>(p_z, fc1_w, fc1_b, p_z1,
                                              NG, 256, 1024, 1024, 1);
    k_gemm<<<dim3(256 / 64, NG / 64), 256>>>(p_z1, fc2_w, fc2_b, p_z2,
                                             NG, 1024, 256, 256, 1);
    k_out<<<(NG * 32 + TB - 1) / TB, TB>>>(out_w, out_b, out);

    // restore zero state for next replay
    k_cleanup<<<(NN + TB - 1) / TB, TB>>>();
}